// round 13
// baseline (speedup 1.0000x reference)
#include <cuda_runtime.h>
#include <cuda_fp16.h>
#include <cstdint>

#define BN 8
#define IC 512
#define OC 512
#define HH 32
#define WW 32

#define RC_DENSE 0.04419417382415922f     // 1/sqrt(512)
#define RC_CONV  0.014731391274719739f    // 1/sqrt(9*512)

// ---------------- device scratch (no runtime allocation) ----------------
__device__ float g_style[BN * IC];
__device__ float g_scale[BN * OC];
__device__ float g_ss[IC * OC];
// weights transposed to [tap][oc][ic], fp16
__device__ __align__(128) __half g_wq[9 * OC * IC];
// modulated input in NHWC: [b][h][w][ic], fp16
__device__ __align__(128) __half g_xm[BN * HH * WW * IC];

// ---------------- prologue kernels ----------------
__global__ void style_kernel(const float* __restrict__ w,
                             const float* __restrict__ dense_w,
                             const float* __restrict__ dense_b) {
    __shared__ float wrow[IC];
    int b = blockIdx.x;
    for (int j = threadIdx.x; j < IC; j += blockDim.x) wrow[j] = w[b * IC + j];
    __syncthreads();
    for (int i = threadIdx.x; i < IC; i += blockDim.x) {
        float acc = 0.f;
        #pragma unroll 8
        for (int j = 0; j < IC; j++) acc = fmaf(wrow[j], dense_w[j * IC + i], acc);
        g_style[b * IC + i] = RC_DENSE * acc + dense_b[i] + 1.0f;
    }
}

// conv_w[k][ic][oc] -> wq[k][oc][ic] (fp16) AND ss[ic][oc] = sum_k w^2 (fused)
__global__ void wtrans_kernel(const float* __restrict__ conv_w) {
    __shared__ float tile[32][33];
    int ic0 = blockIdx.x * 32, oc0 = blockIdx.y * 32;
    int t = threadIdx.x, col = t & 31, row0 = t >> 5;
    int r = t >> 3, pp = t & 7;
    float ssacc[4] = {0.f, 0.f, 0.f, 0.f};
    for (int k = 0; k < 9; k++) {
        __syncthreads();
        #pragma unroll
        for (int rr = 0; rr < 4; rr++) {
            int i = rr * 8 + row0;  // ic
            float v = conv_w[((size_t)(k * IC + ic0 + i)) * OC + oc0 + col];
            tile[i][col] = v;
            ssacc[rr] = fmaf(v, v, ssacc[rr]);
        }
        __syncthreads();
        size_t base = ((size_t)(k * OC + oc0 + r)) * IC + ic0;
        #pragma unroll
        for (int it = 0; it < 2; it++) {
            int ci = 2 * (it * 8 + pp);
            *(__half2*)(g_wq + base + ci) =
                __halves2half2(__float2half_rn(tile[ci][r]), __float2half_rn(tile[ci + 1][r]));
        }
    }
    #pragma unroll
    for (int rr = 0; rr < 4; rr++)
        g_ss[(size_t)(ic0 + rr * 8 + row0) * OC + oc0 + col] = ssacc[rr];
}

__global__ void demod_kernel() {
    __shared__ float s2[IC];
    int b = blockIdx.x;
    for (int i = threadIdx.x; i < IC; i += blockDim.x) {
        float s = g_style[b * IC + i];
        s2[i] = s * s;
    }
    __syncthreads();
    for (int oc = threadIdx.x; oc < OC; oc += blockDim.x) {
        float acc = 0.f;
        #pragma unroll 8
        for (int i = 0; i < IC; i++) acc = fmaf(s2[i], g_ss[i * OC + oc], acc);
        g_scale[b * OC + oc] = RC_CONV * rsqrtf(RC_CONV * RC_CONV * acc + 1e-8f);
    }
}

// x[b][ic][h][w] * style[b][ic] -> xm[b][h][w][ic] (fp16)
__global__ void xtrans_kernel(const float* __restrict__ x) {
    __shared__ float tile[32][33];
    int ic0 = blockIdx.x * 32, h = blockIdx.y, b = blockIdx.z;
    int t = threadIdx.x, col = t & 31, row0 = t >> 5;
    #pragma unroll
    for (int rr = 0; rr < 4; rr++) {
        int i = rr * 8 + row0;  // ic
        tile[i][col] = x[(((size_t)b * IC + ic0 + i) * HH + h) * WW + col] * g_style[b * IC + ic0 + i];
    }
    __syncthreads();
    int w = t >> 3, pp = t & 7;
    size_t base = (((size_t)b * HH + h) * WW + w) * IC + ic0;
    #pragma unroll
    for (int it = 0; it < 2; it++) {
        int ci = 2 * (it * 8 + pp);
        *(__half2*)(g_xm + base + ci) =
            __halves2half2(__float2half_rn(tile[ci][w]), __float2half_rn(tile[ci + 1][w]));
    }
}

// ---------------- main mma.sync conv kernel ----------------
// CTA tile: M=128 (4 h x 32 w) x N=128 oc. 8 warps (4 M x 2 N), warp 32x64.
// Tap-group pipeline: 3 taps per barrier. B staged as two ping-pong 3-tap
// slabs; A halo double-buffered per chunk (prefetched with the last group of
// the previous chunk). One wait_group 0 + one __syncthreads per group (48
// total), prefetch has a full group of compute cover.
#define KC 32
#define PAD_A 40
#define PAD_B 40

// smem offsets in halves
#define A_SZ 8160                       // 204 * 40
#define A_O(buf) ((buf) * A_SZ)
#define B_SLAB 15360                    // 3 taps * 128 * 40
#define B_O(half) (16320 + (half) * B_SLAB)
#define SM_HALVES 47040                 // 94080 bytes

__device__ __forceinline__ void mma_f16(float* c,
                                        const uint32_t* a, uint32_t b0, uint32_t b1) {
    asm volatile(
        "mma.sync.aligned.m16n8k16.row.col.f32.f16.f16.f32 "
        "{%0,%1,%2,%3}, {%4,%5,%6,%7}, {%8,%9}, {%0,%1,%2,%3};"
        : "+f"(c[0]), "+f"(c[1]), "+f"(c[2]), "+f"(c[3])
        : "r"(a[0]), "r"(a[1]), "r"(a[2]), "r"(a[3]), "r"(b0), "r"(b1));
}

__device__ __forceinline__ void ldsm4(uint32_t* r, uint32_t a) {
    asm volatile("ldmatrix.sync.aligned.m8n8.x4.shared.b16 {%0,%1,%2,%3}, [%4];"
                 : "=r"(r[0]), "=r"(r[1]), "=r"(r[2]), "=r"(r[3]) : "r"(a));
}

__device__ __forceinline__ void cp16(uint32_t dst, const void* src, bool v) {
    asm volatile("cp.async.ca.shared.global [%0], [%1], 16, %2;"
                 :: "r"(dst), "l"(src), "r"(v ? 16 : 0) : "memory");
}
#define CP_COMMIT() asm volatile("cp.async.commit_group;" ::: "memory")
#define CP_WAIT0()  asm volatile("cp.async.wait_group 0;" ::: "memory")

__device__ __forceinline__ uint32_t smem_u32(const void* p) {
    uint32_t a;
    asm("{ .reg .u64 t; cvta.to.shared.u64 t, %1; cvt.u32.u64 %0, t; }" : "=r"(a) : "l"(p));
    return a;
}

__global__ __launch_bounds__(256, 2)
void conv_mma_kernel(float* __restrict__ y) {
    extern __shared__ unsigned short sm[];
    const uint32_t smb = smem_u32(sm);

    const int tid = threadIdx.x;
    const int wid = tid >> 5, lane = tid & 31;
    const int gr = lane >> 2, tig = lane & 3;
    const int wm = wid & 3;        // warp h-row
    const int wn = wid >> 2;       // warp oc half

    const int h0 = blockIdx.x * 4;
    const int oc0 = blockIdx.y * 128;
    const int b = blockIdx.z;

    // ---- ldmatrix lane address components ----
    const int r16 = ((lane >> 3) & 1) * 8 + (lane & 7);
    const int kq8 = (lane >> 4) * 8;
    const int aoff0 = ((wm + 1) * 34 + r16 + 1) * PAD_A + kq8;
    const int rb = (lane & 7) + ((lane >> 4) & 1) * 8;
    const int kb8 = ((lane >> 3) & 1) * 8;
    const int boff = (wn * 64 + rb) * PAD_B + kb8;

    // ---- A halo loader coords (204 positions x 64B) ----
    const int p = tid;
    const bool pa = p < 204;
    const int hi_ = p / 34, wi_ = p % 34;
    const int ha = h0 + hi_ - 1, wa = wi_ - 1;
    const bool va = pa && ((unsigned)ha < HH) && ((unsigned)wa < WW);
    const size_t aidx = (((size_t)b * HH + (va ? ha : 0)) * WW + (va ? wa : 0)) * IC;
    const uint32_t adst = smb + (uint32_t)(p * PAD_A) * 2;

    // ---- B loader coords: 2 threads per row, 32B each ----
    const int rB = tid >> 1, halfB = tid & 1;
    const size_t bRowBase = (size_t)(oc0 + rB) * IC + halfB * 16;
    const uint32_t bdst = (uint32_t)(rB * PAD_B + halfB * 16) * 2;

    float acc[2][8][4];
    #pragma unroll
    for (int mt = 0; mt < 2; mt++)
        #pragma unroll
        for (int nt = 0; nt < 8; nt++)
            #pragma unroll
            for (int q = 0; q < 4; q++) acc[mt][nt][q] = 0.f;

    // ---- prefetch helpers ----
    auto issueA = [&](int tcc, int tbuf) {
        if (pa) {
            uint32_t d_ = adst + (uint32_t)(tbuf * A_SZ) * 2;
            #pragma unroll
            for (int j = 0; j < 4; j++)
                cp16(d_ + j * 16, g_xm + aidx + tcc * KC + j * 8, va);
        }
    };
    auto issueB = [&](int tcc, int tgi, int thalf) {
        #pragma unroll
        for (int j = 0; j < 3; j++) {
            const size_t src = (size_t)(tgi * 3 + j) * OC * IC + bRowBase + tcc * KC;
            uint32_t d_ = smb + (uint32_t)(B_O(thalf) + j * 5120) * 2 + bdst;
            cp16(d_, g_wq + src, true);
            cp16(d_ + 16, g_wq + src + 8, true);
        }
    };

    // prologue: A chunk0 + B group(0,0) -> half0, one commit
    issueA(0, 0);
    issueB(0, 0, 0);
    CP_COMMIT();

    for (int cc = 0; cc < 16; cc++) {
        const int abuf = cc & 1;
        #pragma unroll
        for (int gi = 0; gi < 3; gi++) {
            const int half = (cc + gi) & 1;
            CP_WAIT0();
            __syncthreads();

            // prefetch next group into other half (+ next chunk's A at gi==2)
            if (!(cc == 15 && gi == 2)) {
                const int ncc = (gi == 2) ? cc + 1 : cc;
                const int ngi = (gi + 1) % 3;
                issueB(ncc, ngi, half ^ 1);
                if (gi == 2) issueA(ncc, ncc & 1);
                CP_COMMIT();
            }

            // compute taps gi*3 .. gi*3+2 from this half
            #pragma unroll
            for (int j = 0; j < 3; j++) {
                const int tsh = ((gi - 1) * 34 + (j - 1)) * PAD_A;
                const uint32_t bbase = smb + (uint32_t)(B_O(half) + j * 5120 + boff) * 2;
                const uint32_t abase = smb + (uint32_t)(aoff0 + abuf * A_SZ + tsh) * 2;
                #pragma unroll
                for (int ks = 0; ks < 2; ks++) {
                    uint32_t ah[2][4];
                    #pragma unroll
                    for (int mt = 0; mt < 2; mt++)
                        ldsm4(ah[mt], abase + (uint32_t)(mt * 16 * PAD_A + ks * 16) * 2);
                    #pragma unroll
                    for (int np = 0; np < 4; np++) {
                        uint32_t bh[4];
                        ldsm4(bh, bbase + (uint32_t)(np * 16 * PAD_B + ks * 16) * 2);
                        // same-accumulator distance = 4
                        mma_f16(acc[0][2 * np],     ah[0], bh[0], bh[1]);
                        mma_f16(acc[1][2 * np],     ah[1], bh[0], bh[1]);
                        mma_f16(acc[0][2 * np + 1], ah[0], bh[2], bh[3]);
                        mma_f16(acc[1][2 * np + 1], ah[1], bh[2], bh[3]);
                    }
                }
            }
        }
    }

    // ---- epilogue: demodulate + store ----
    const int h = h0 + wm;
    float scl[8][2];
    #pragma unroll
    for (int nt = 0; nt < 8; nt++) {
        int oc = oc0 + wn * 64 + nt * 8 + tig * 2;
        scl[nt][0] = g_scale[b * OC + oc];
        scl[nt][1] = g_scale[b * OC + oc + 1];
    }
    #pragma unroll
    for (int mt = 0; mt < 2; mt++) {
        int w0 = mt * 16 + gr;
        #pragma unroll
        for (int nt = 0; nt < 8; nt++) {
            int oc = oc0 + wn * 64 + nt * 8 + tig * 2;
            size_t base0 = (((size_t)b * OC + oc) * HH + h) * WW;
            size_t base1 = base0 + (size_t)HH * WW;
            y[base0 + w0]     = acc[mt][nt][0] * scl[nt][0];
            y[base1 + w0]     = acc[mt][nt][1] * scl[nt][1];
            y[base0 + w0 + 8] = acc[mt][nt][2] * scl[nt][0];
            y[base1 + w0 + 8] = acc[mt][nt][3] * scl[nt][1];
        }
    }
}

// ---------------------------------------------------------------------------
extern "C" void kernel_launch(void* const* d_in, const int* in_sizes, int n_in,
                              void* d_out, int out_size) {
    const float* x       = (const float*)d_in[0];
    const float* w       = (const float*)d_in[1];
    const float* conv_w  = (const float*)d_in[2];
    const float* dense_w = (const float*)d_in[3];
    const float* dense_b = (const float*)d_in[4];
    float* y = (float*)d_out;

    style_kernel<<<BN, 256>>>(w, dense_w, dense_b);
    wtrans_kernel<<<dim3(IC / 32, OC / 32), 256>>>(conv_w);   // + fused ss
    demod_kernel<<<BN, 512>>>();
    xtrans_kernel<<<dim3(IC / 32, HH, BN), 256>>>(x);

    static bool attr_set = false;
    if (!attr_set) {
        cudaFuncSetAttribute(conv_mma_kernel,
                             cudaFuncAttributeMaxDynamicSharedMemorySize, SM_HALVES * 2);
        attr_set = true;
    }
    conv_mma_kernel<<<dim3(8, 4, BN), 256, SM_HALVES * 2>>>(y);
}

// round 14
// speedup vs baseline: 1.5368x; 1.5368x over previous
#include <cuda_runtime.h>
#include <cuda_fp16.h>
#include <cstdint>

#define BN 8
#define IC 512
#define OC 512
#define HH 32
#define WW 32

#define RC_DENSE 0.04419417382415922f     // 1/sqrt(512)
#define RC_CONV  0.014731391274719739f    // 1/sqrt(9*512)

// ---------------- device scratch (no runtime allocation) ----------------
__device__ float g_style[BN * IC];
__device__ float g_scale[BN * OC];
__device__ float g_ss[IC * OC];
// weights transposed to [tap][oc][ic], fp16
__device__ __align__(128) __half g_wq[9 * OC * IC];
// modulated input in NHWC: [b][h][w][ic], fp16
__device__ __align__(128) __half g_xm[BN * HH * WW * IC];

// ---------------- prologue kernels ----------------
__global__ void style_kernel(const float* __restrict__ w,
                             const float* __restrict__ dense_w,
                             const float* __restrict__ dense_b) {
    __shared__ float wrow[IC];
    int b = blockIdx.x;
    for (int j = threadIdx.x; j < IC; j += blockDim.x) wrow[j] = w[b * IC + j];
    __syncthreads();
    for (int i = threadIdx.x; i < IC; i += blockDim.x) {
        float acc = 0.f;
        #pragma unroll 8
        for (int j = 0; j < IC; j++) acc = fmaf(wrow[j], dense_w[j * IC + i], acc);
        g_style[b * IC + i] = RC_DENSE * acc + dense_b[i] + 1.0f;
    }
}

// conv_w[k][ic][oc] -> wq[k][oc][ic] (fp16) AND ss[ic][oc] = sum_k w^2 (fused)
__global__ void wtrans_kernel(const float* __restrict__ conv_w) {
    __shared__ float tile[32][33];
    int ic0 = blockIdx.x * 32, oc0 = blockIdx.y * 32;
    int t = threadIdx.x, col = t & 31, row0 = t >> 5;
    int r = t >> 3, pp = t & 7;
    float ssacc[4] = {0.f, 0.f, 0.f, 0.f};
    for (int k = 0; k < 9; k++) {
        __syncthreads();
        #pragma unroll
        for (int rr = 0; rr < 4; rr++) {
            int i = rr * 8 + row0;  // ic
            float v = conv_w[((size_t)(k * IC + ic0 + i)) * OC + oc0 + col];
            tile[i][col] = v;
            ssacc[rr] = fmaf(v, v, ssacc[rr]);
        }
        __syncthreads();
        size_t base = ((size_t)(k * OC + oc0 + r)) * IC + ic0;
        #pragma unroll
        for (int it = 0; it < 2; it++) {
            int ci = 2 * (it * 8 + pp);
            *(__half2*)(g_wq + base + ci) =
                __halves2half2(__float2half_rn(tile[ci][r]), __float2half_rn(tile[ci + 1][r]));
        }
    }
    #pragma unroll
    for (int rr = 0; rr < 4; rr++)
        g_ss[(size_t)(ic0 + rr * 8 + row0) * OC + oc0 + col] = ssacc[rr];
}

__global__ void demod_kernel() {
    __shared__ float s2[IC];
    int b = blockIdx.x;
    for (int i = threadIdx.x; i < IC; i += blockDim.x) {
        float s = g_style[b * IC + i];
        s2[i] = s * s;
    }
    __syncthreads();
    for (int oc = threadIdx.x; oc < OC; oc += blockDim.x) {
        float acc = 0.f;
        #pragma unroll 8
        for (int i = 0; i < IC; i++) acc = fmaf(s2[i], g_ss[i * OC + oc], acc);
        g_scale[b * OC + oc] = RC_CONV * rsqrtf(RC_CONV * RC_CONV * acc + 1e-8f);
    }
}

// x[b][ic][h][w] * style[b][ic] -> xm[b][h][w][ic] (fp16)
__global__ void xtrans_kernel(const float* __restrict__ x) {
    __shared__ float tile[32][33];
    int ic0 = blockIdx.x * 32, h = blockIdx.y, b = blockIdx.z;
    int t = threadIdx.x, col = t & 31, row0 = t >> 5;
    #pragma unroll
    for (int rr = 0; rr < 4; rr++) {
        int i = rr * 8 + row0;  // ic
        tile[i][col] = x[(((size_t)b * IC + ic0 + i) * HH + h) * WW + col] * g_style[b * IC + ic0 + i];
    }
    __syncthreads();
    int w = t >> 3, pp = t & 7;
    size_t base = (((size_t)b * HH + h) * WW + w) * IC + ic0;
    #pragma unroll
    for (int it = 0; it < 2; it++) {
        int ci = 2 * (it * 8 + pp);
        *(__half2*)(g_xm + base + ci) =
            __halves2half2(__float2half_rn(tile[ci][w]), __float2half_rn(tile[ci + 1][w]));
    }
}

// ---------------- main mma.sync conv kernel (R8 configuration) ----------------
// CTA tile: M=128 (4 h x 32 w) x N=128 oc. 8 warps (4 M x 2 N), warp 32x64.
// A staged once per ic-chunk as 6x34 halo (single fp16); B(tap) fp16,
// 3-stage cp.async pipeline (prefetch depth 2). Single-term fp16 MMA.
#define KC 32
#define PAD_A 40
#define PAD_B 40

// smem offsets in halves
#define A_O 0
#define B_O(buf) (8160 + (buf) * 5120)
#define SM_HALVES 23520      // 47040 bytes

__device__ __forceinline__ void mma_f16(float* c,
                                        const uint32_t* a, uint32_t b0, uint32_t b1) {
    asm volatile(
        "mma.sync.aligned.m16n8k16.row.col.f32.f16.f16.f32 "
        "{%0,%1,%2,%3}, {%4,%5,%6,%7}, {%8,%9}, {%0,%1,%2,%3};"
        : "+f"(c[0]), "+f"(c[1]), "+f"(c[2]), "+f"(c[3])
        : "r"(a[0]), "r"(a[1]), "r"(a[2]), "r"(a[3]), "r"(b0), "r"(b1));
}

__device__ __forceinline__ void ldsm4(uint32_t* r, uint32_t a) {
    asm volatile("ldmatrix.sync.aligned.m8n8.x4.shared.b16 {%0,%1,%2,%3}, [%4];"
                 : "=r"(r[0]), "=r"(r[1]), "=r"(r[2]), "=r"(r[3]) : "r"(a));
}

__device__ __forceinline__ void cp16(uint32_t dst, const void* src, bool v) {
    asm volatile("cp.async.ca.shared.global [%0], [%1], 16, %2;"
                 :: "r"(dst), "l"(src), "r"(v ? 16 : 0) : "memory");
}
#define CP_COMMIT() asm volatile("cp.async.commit_group;" ::: "memory")
#define CP_WAIT0()  asm volatile("cp.async.wait_group 0;" ::: "memory")
#define CP_WAIT1()  asm volatile("cp.async.wait_group 1;" ::: "memory")

__device__ __forceinline__ uint32_t smem_u32(const void* p) {
    uint32_t a;
    asm("{ .reg .u64 t; cvta.to.shared.u64 t, %1; cvt.u32.u64 %0, t; }" : "=r"(a) : "l"(p));
    return a;
}

__global__ __launch_bounds__(256, 2)
void conv_mma_kernel(float* __restrict__ y) {
    extern __shared__ unsigned short sm[];
    const uint32_t smb = smem_u32(sm);

    const int tid = threadIdx.x;
    const int wid = tid >> 5, lane = tid & 31;
    const int gr = lane >> 2, tig = lane & 3;
    const int wm = wid & 3;        // warp h-row
    const int wn = wid >> 2;       // warp oc half

    const int h0 = blockIdx.x * 4;
    const int oc0 = blockIdx.y * 128;
    const int b = blockIdx.z;

    // ---- ldmatrix lane address components ----
    const int r16 = ((lane >> 3) & 1) * 8 + (lane & 7);
    const int kq8 = (lane >> 4) * 8;
    int aoff0 = ((wm + 1) * 34 + r16 + 1) * PAD_A + kq8;
    const int rb = (lane & 7) + ((lane >> 4) & 1) * 8;
    const int kb8 = ((lane >> 3) & 1) * 8;
    const int boff = (wn * 64 + rb) * PAD_B + kb8;

    // ---- A halo loader coords (204 positions) ----
    const int p = tid;
    const bool pa = p < 204;
    const int hi_ = p / 34, wi_ = p % 34;
    const int ha = h0 + hi_ - 1, wa = wi_ - 1;
    const bool va = pa && ((unsigned)ha < HH) && ((unsigned)wa < WW);
    const size_t aidx = (((size_t)b * HH + (va ? ha : 0)) * WW + (va ? wa : 0)) * IC;
    const uint32_t adst = smb + (uint32_t)(A_O + p * PAD_A) * 2;

    // ---- B loader coords ----
    const int rB = tid >> 1, halfB = tid & 1;
    const size_t bRowBase = (size_t)(oc0 + rB) * IC + halfB * 16;
    const uint32_t bdst = (uint32_t)(rB * PAD_B + halfB * 16) * 2;

    float acc[2][8][4];
    #pragma unroll
    for (int mt = 0; mt < 2; mt++)
        #pragma unroll
        for (int nt = 0; nt < 8; nt++)
            #pragma unroll
            for (int q = 0; q < 4; q++) acc[mt][nt][q] = 0.f;

    for (int cc = 0; cc < 16; cc++) {
        const int ic0 = cc * KC;
        __syncthreads();   // protect A halo + B buffers from previous chunk's readers

        // group 0: A halo + B tap0 -> buf0
        if (pa) {
            #pragma unroll
            for (int j = 0; j < 4; j++)
                cp16(adst + j * 16, g_xm + aidx + ic0 + j * 8, va);
        }
        {
            const size_t src = bRowBase + ic0;
            uint32_t d_ = smb + (uint32_t)B_O(0) * 2 + bdst;
            cp16(d_,      g_wq + src, true);
            cp16(d_ + 16, g_wq + src + 8, true);
        }
        CP_COMMIT();
        // group 1: B tap1 -> buf1
        {
            const size_t src = (size_t)OC * IC + bRowBase + ic0;
            uint32_t d_ = smb + (uint32_t)B_O(1) * 2 + bdst;
            cp16(d_,      g_wq + src, true);
            cp16(d_ + 16, g_wq + src + 8, true);
        }
        CP_COMMIT();

        #pragma unroll
        for (int kk = 0; kk < 9; kk++) {
            if (kk < 7) { CP_WAIT1(); } else { CP_WAIT0(); }
            __syncthreads();
            if (kk < 7) {   // prefetch tap kk+2 -> buf (kk+2)%3
                const size_t src = (size_t)(kk + 2) * OC * IC + bRowBase + ic0;
                uint32_t d_ = smb + (uint32_t)B_O((kk + 2) % 3) * 2 + bdst;
                cp16(d_,      g_wq + src, true);
                cp16(d_ + 16, g_wq + src + 8, true);
                CP_COMMIT();
            }

            // ---- compute tap kk from buf kk%3 ----
            const int dh = kk / 3 - 1, dw = kk % 3 - 1;
            const int tsh = (dh * 34 + dw) * PAD_A;
            const uint32_t bbase = smb + (uint32_t)(B_O(kk % 3) + boff) * 2;

            #pragma unroll
            for (int ks = 0; ks < 2; ks++) {
                uint32_t ah[2][4];
                #pragma unroll
                for (int mt = 0; mt < 2; mt++) {
                    uint32_t aa = smb + (uint32_t)(aoff0 + mt * 16 * PAD_A + tsh + ks * 16) * 2;
                    ldsm4(ah[mt], aa);
                }
                #pragma unroll
                for (int np = 0; np < 4; np++) {
                    uint32_t bh[4];
                    uint32_t ba = bbase + (uint32_t)(np * 16 * PAD_B + ks * 16) * 2;
                    ldsm4(bh, ba);
                    // same-accumulator distance = 4
                    mma_f16(acc[0][2 * np],     ah[0], bh[0], bh[1]);
                    mma_f16(acc[1][2 * np],     ah[1], bh[0], bh[1]);
                    mma_f16(acc[0][2 * np + 1], ah[0], bh[2], bh[3]);
                    mma_f16(acc[1][2 * np + 1], ah[1], bh[2], bh[3]);
                }
            }
        }
    }

    // ---- epilogue: demodulate + store ----
    const int h = h0 + wm;
    float scl[8][2];
    #pragma unroll
    for (int nt = 0; nt < 8; nt++) {
        int oc = oc0 + wn * 64 + nt * 8 + tig * 2;
        scl[nt][0] = g_scale[b * OC + oc];
        scl[nt][1] = g_scale[b * OC + oc + 1];
    }
    #pragma unroll
    for (int mt = 0; mt < 2; mt++) {
        int w0 = mt * 16 + gr;
        #pragma unroll
        for (int nt = 0; nt < 8; nt++) {
            int oc = oc0 + wn * 64 + nt * 8 + tig * 2;
            size_t base0 = (((size_t)b * OC + oc) * HH + h) * WW;
            size_t base1 = base0 + (size_t)HH * WW;
            y[base0 + w0]     = acc[mt][nt][0] * scl[nt][0];
            y[base1 + w0]     = acc[mt][nt][1] * scl[nt][1];
            y[base0 + w0 + 8] = acc[mt][nt][2] * scl[nt][0];
            y[base1 + w0 + 8] = acc[mt][nt][3] * scl[nt][1];
        }
    }
}

// ---------------------------------------------------------------------------
extern "C" void kernel_launch(void* const* d_in, const int* in_sizes, int n_in,
                              void* d_out, int out_size) {
    const float* x       = (const float*)d_in[0];
    const float* w       = (const float*)d_in[1];
    const float* conv_w  = (const float*)d_in[2];
    const float* dense_w = (const float*)d_in[3];
    const float* dense_b = (const float*)d_in[4];
    float* y = (float*)d_out;

    style_kernel<<<BN, 256>>>(w, dense_w, dense_b);
    wtrans_kernel<<<dim3(IC / 32, OC / 32), 256>>>(conv_w);   // + fused ss
    demod_kernel<<<BN, 512>>>();
    xtrans_kernel<<<dim3(IC / 32, HH, BN), 256>>>(x);

    static bool attr_set = false;
    if (!attr_set) {
        cudaFuncSetAttribute(conv_mma_kernel,
                             cudaFuncAttributeMaxDynamicSharedMemorySize, SM_HALVES * 2);
        attr_set = true;
    }
    conv_mma_kernel<<<dim3(8, 4, BN), 256, SM_HALVES * 2>>>(y);
}

// round 15
// speedup vs baseline: 1.6819x; 1.0944x over previous
#include <cuda_runtime.h>
#include <cuda_fp16.h>
#include <cstdint>

#define BN 8
#define IC 512
#define OC 512
#define HH 32
#define WW 32

#define RC_DENSE 0.04419417382415922f     // 1/sqrt(512)
#define RC_CONV  0.014731391274719739f    // 1/sqrt(9*512)

// ---------------- device scratch (no runtime allocation) ----------------
__device__ float g_style[BN * IC];
__device__ float g_scale[BN * OC];
__device__ float g_ss[IC * OC];
// weights transposed to [tap][oc][ic], fp16
__device__ __align__(128) __half g_wq[9 * OC * IC];
// modulated input in NHWC: [b][h][w][ic], fp16
__device__ __align__(128) __half g_xm[BN * HH * WW * IC];

// ---------------- prologue kernels ----------------
__global__ void style_kernel(const float* __restrict__ w,
                             const float* __restrict__ dense_w,
                             const float* __restrict__ dense_b) {
    __shared__ float wrow[IC];
    int b = blockIdx.x;
    for (int j = threadIdx.x; j < IC; j += blockDim.x) wrow[j] = w[b * IC + j];
    __syncthreads();
    for (int i = threadIdx.x; i < IC; i += blockDim.x) {
        float acc = 0.f;
        #pragma unroll 8
        for (int j = 0; j < IC; j++) acc = fmaf(wrow[j], dense_w[j * IC + i], acc);
        g_style[b * IC + i] = RC_DENSE * acc + dense_b[i] + 1.0f;
    }
}

__global__ void ss_kernel(const float* __restrict__ conv_w) {
    int idx = blockIdx.x * blockDim.x + threadIdx.x;
    if (idx >= IC * OC) return;
    float s = 0.f;
    #pragma unroll
    for (int k = 0; k < 9; k++) {
        float v = conv_w[k * IC * OC + idx];
        s = fmaf(v, v, s);
    }
    g_ss[idx] = s;
}

// demod v2: grid 16 blocks x 256 threads; all 8 batches per block; ss read once.
__global__ __launch_bounds__(256)
void demod_kernel() {
    __shared__ float s2[BN * IC];          // 16 KB
    __shared__ float part[8 * BN * 32];    // 8 KB: [oct][b][oc_l]
    const int t = threadIdx.x;
    const int oc0 = blockIdx.x * 32;

    for (int e = t; e < BN * IC; e += 256) {
        float s = g_style[e];
        s2[e] = s * s;
    }
    __syncthreads();

    const int oc_l = t & 31, oct = t >> 5;
    float acc[BN];
    #pragma unroll
    for (int b = 0; b < BN; b++) acc[b] = 0.f;
    for (int ic = oct * 64; ic < oct * 64 + 64; ic++) {
        float ssv = g_ss[(size_t)ic * OC + oc0 + oc_l];
        #pragma unroll
        for (int b = 0; b < BN; b++) acc[b] = fmaf(s2[b * IC + ic], ssv, acc[b]);
    }
    #pragma unroll
    for (int b = 0; b < BN; b++) part[(oct * BN + b) * 32 + oc_l] = acc[b];
    __syncthreads();

    // 256 threads = 8 b x 32 oc_l: sum the 8 octants
    const int b = t >> 5, ocl2 = t & 31;
    float s = 0.f;
    #pragma unroll
    for (int o = 0; o < 8; o++) s += part[(o * BN + b) * 32 + ocl2];
    g_scale[b * OC + oc0 + ocl2] = RC_CONV * rsqrtf(RC_CONV * RC_CONV * s + 1e-8f);
}

// conv_w[k][ic][oc] -> wq[k][oc][ic] (fp16)
__global__ void wtrans_kernel(const float* __restrict__ conv_w) {
    __shared__ float tile[32][33];
    int ic0 = blockIdx.x * 32, oc0 = blockIdx.y * 32, k = blockIdx.z;
    int t = threadIdx.x, col = t & 31, row0 = t >> 5;
    #pragma unroll
    for (int rr = 0; rr < 4; rr++) {
        int i = rr * 8 + row0;  // ic
        tile[i][col] = conv_w[((size_t)(k * IC + ic0 + i)) * OC + oc0 + col];
    }
    __syncthreads();
    int r = t >> 3, pp = t & 7;  // r = oc row within tile
    size_t base = ((size_t)(k * OC + oc0 + r)) * IC + ic0;
    #pragma unroll
    for (int it = 0; it < 2; it++) {
        int ci = 2 * (it * 8 + pp);
        *(__half2*)(g_wq + base + ci) =
            __halves2half2(__float2half_rn(tile[ci][r]), __float2half_rn(tile[ci + 1][r]));
    }
}

// xtrans v2: x[b][ic][h][w] * style -> xm[b][h][w][ic]; 8B stores, conflict-free
__global__ void xtrans_kernel(const float* __restrict__ x) {
    __shared__ float tile[32][33];
    int ic0 = blockIdx.x * 32, h = blockIdx.y, b = blockIdx.z;
    int t = threadIdx.x, col = t & 31, row0 = t >> 5;
    #pragma unroll
    for (int rr = 0; rr < 4; rr++) {
        int i = rr * 8 + row0;  // ic
        tile[i][col] = x[(((size_t)b * IC + ic0 + i) * HH + h) * WW + col] * g_style[b * IC + ic0 + i];
    }
    __syncthreads();
    // store: thread -> (w = t>>3, seg = t&7), 4 consecutive ic (8 bytes)
    int w = t >> 3, seg = t & 7;
    __half h0 = __float2half_rn(tile[seg * 4 + 0][w]);
    __half h1 = __float2half_rn(tile[seg * 4 + 1][w]);
    __half h2 = __float2half_rn(tile[seg * 4 + 2][w]);
    __half h3 = __float2half_rn(tile[seg * 4 + 3][w]);
    uint2 pk;
    pk.x = (uint32_t)__half_as_ushort(h0) | ((uint32_t)__half_as_ushort(h1) << 16);
    pk.y = (uint32_t)__half_as_ushort(h2) | ((uint32_t)__half_as_ushort(h3) << 16);
    size_t base = (((size_t)b * HH + h) * WW + w) * IC + ic0 + seg * 4;
    *(uint2*)(g_xm + base) = pk;
}

// ---------------- main mma.sync conv kernel (R8 configuration, unchanged) ----
// CTA tile: M=128 (4 h x 32 w) x N=128 oc. 8 warps (4 M x 2 N), warp 32x64.
// A staged once per ic-chunk as 6x34 halo (single fp16); B(tap) fp16,
// 3-stage cp.async pipeline (prefetch depth 2). Single-term fp16 MMA.
#define KC 32
#define PAD_A 40
#define PAD_B 40

// smem offsets in halves
#define A_O 0
#define B_O(buf) (8160 + (buf) * 5120)
#define SM_HALVES 23520      // 47040 bytes

__device__ __forceinline__ void mma_f16(float* c,
                                        const uint32_t* a, uint32_t b0, uint32_t b1) {
    asm volatile(
        "mma.sync.aligned.m16n8k16.row.col.f32.f16.f16.f32 "
        "{%0,%1,%2,%3}, {%4,%5,%6,%7}, {%8,%9}, {%0,%1,%2,%3};"
        : "+f"(c[0]), "+f"(c[1]), "+f"(c[2]), "+f"(c[3])
        : "r"(a[0]), "r"(a[1]), "r"(a[2]), "r"(a[3]), "r"(b0), "r"(b1));
}

__device__ __forceinline__ void ldsm4(uint32_t* r, uint32_t a) {
    asm volatile("ldmatrix.sync.aligned.m8n8.x4.shared.b16 {%0,%1,%2,%3}, [%4];"
                 : "=r"(r[0]), "=r"(r[1]), "=r"(r[2]), "=r"(r[3]) : "r"(a));
}

__device__ __forceinline__ void cp16(uint32_t dst, const void* src, bool v) {
    asm volatile("cp.async.ca.shared.global [%0], [%1], 16, %2;"
                 :: "r"(dst), "l"(src), "r"(v ? 16 : 0) : "memory");
}
#define CP_COMMIT() asm volatile("cp.async.commit_group;" ::: "memory")
#define CP_WAIT0()  asm volatile("cp.async.wait_group 0;" ::: "memory")
#define CP_WAIT1()  asm volatile("cp.async.wait_group 1;" ::: "memory")

__device__ __forceinline__ uint32_t smem_u32(const void* p) {
    uint32_t a;
    asm("{ .reg .u64 t; cvta.to.shared.u64 t, %1; cvt.u32.u64 %0, t; }" : "=r"(a) : "l"(p));
    return a;
}

__global__ __launch_bounds__(256, 2)
void conv_mma_kernel(float* __restrict__ y) {
    extern __shared__ unsigned short sm[];
    const uint32_t smb = smem_u32(sm);

    const int tid = threadIdx.x;
    const int wid = tid >> 5, lane = tid & 31;
    const int gr = lane >> 2, tig = lane & 3;
    const int wm = wid & 3;        // warp h-row
    const int wn = wid >> 2;       // warp oc half

    const int h0 = blockIdx.x * 4;
    const int oc0 = blockIdx.y * 128;
    const int b = blockIdx.z;

    // ---- ldmatrix lane address components ----
    const int r16 = ((lane >> 3) & 1) * 8 + (lane & 7);
    const int kq8 = (lane >> 4) * 8;
    int aoff0 = ((wm + 1) * 34 + r16 + 1) * PAD_A + kq8;
    const int rb = (lane & 7) + ((lane >> 4) & 1) * 8;
    const int kb8 = ((lane >> 3) & 1) * 8;
    const int boff = (wn * 64 + rb) * PAD_B + kb8;

    // ---- A halo loader coords (204 positions) ----
    const int p = tid;
    const bool pa = p < 204;
    const int hi_ = p / 34, wi_ = p % 34;
    const int ha = h0 + hi_ - 1, wa = wi_ - 1;
    const bool va = pa && ((unsigned)ha < HH) && ((unsigned)wa < WW);
    const size_t aidx = (((size_t)b * HH + (va ? ha : 0)) * WW + (va ? wa : 0)) * IC;
    const uint32_t adst = smb + (uint32_t)(A_O + p * PAD_A) * 2;

    // ---- B loader coords ----
    const int rB = tid >> 1, halfB = tid & 1;
    const size_t bRowBase = (size_t)(oc0 + rB) * IC + halfB * 16;
    const uint32_t bdst = (uint32_t)(rB * PAD_B + halfB * 16) * 2;

    float acc[2][8][4];
    #pragma unroll
    for (int mt = 0; mt < 2; mt++)
        #pragma unroll
        for (int nt = 0; nt < 8; nt++)
            #pragma unroll
            for (int q = 0; q < 4; q++) acc[mt][nt][q] = 0.f;

    for (int cc = 0; cc < 16; cc++) {
        const int ic0 = cc * KC;
        __syncthreads();   // protect A halo + B buffers from previous chunk's readers

        // group 0: A halo + B tap0 -> buf0
        if (pa) {
            #pragma unroll
            for (int j = 0; j < 4; j++)
                cp16(adst + j * 16, g_xm + aidx + ic0 + j * 8, va);
        }
        {
            const size_t src = bRowBase + ic0;
            uint32_t d_ = smb + (uint32_t)B_O(0) * 2 + bdst;
            cp16(d_,      g_wq + src, true);
            cp16(d_ + 16, g_wq + src + 8, true);
        }
        CP_COMMIT();
        // group 1: B tap1 -> buf1
        {
            const size_t src = (size_t)OC * IC + bRowBase + ic0;
            uint32_t d_ = smb + (uint32_t)B_O(1) * 2 + bdst;
            cp16(d_,      g_wq + src, true);
            cp16(d_ + 16, g_wq + src + 8, true);
        }
        CP_COMMIT();

        #pragma unroll
        for (int kk = 0; kk < 9; kk++) {
            if (kk < 7) { CP_WAIT1(); } else { CP_WAIT0(); }
            __syncthreads();
            if (kk < 7) {   // prefetch tap kk+2 -> buf (kk+2)%3
                const size_t src = (size_t)(kk + 2) * OC * IC + bRowBase + ic0;
                uint32_t d_ = smb + (uint32_t)B_O((kk + 2) % 3) * 2 + bdst;
                cp16(d_,      g_wq + src, true);
                cp16(d_ + 16, g_wq + src + 8, true);
                CP_COMMIT();
            }

            // ---- compute tap kk from buf kk%3 ----
            const int dh = kk / 3 - 1, dw = kk % 3 - 1;
            const int tsh = (dh * 34 + dw) * PAD_A;
            const uint32_t bbase = smb + (uint32_t)(B_O(kk % 3) + boff) * 2;

            #pragma unroll
            for (int ks = 0; ks < 2; ks++) {
                uint32_t ah[2][4];
                #pragma unroll
                for (int mt = 0; mt < 2; mt++) {
                    uint32_t aa = smb + (uint32_t)(aoff0 + mt * 16 * PAD_A + tsh + ks * 16) * 2;
                    ldsm4(ah[mt], aa);
                }
                #pragma unroll
                for (int np = 0; np < 4; np++) {
                    uint32_t bh[4];
                    uint32_t ba = bbase + (uint32_t)(np * 16 * PAD_B + ks * 16) * 2;
                    ldsm4(bh, ba);
                    // same-accumulator distance = 4
                    mma_f16(acc[0][2 * np],     ah[0], bh[0], bh[1]);
                    mma_f16(acc[1][2 * np],     ah[1], bh[0], bh[1]);
                    mma_f16(acc[0][2 * np + 1], ah[0], bh[2], bh[3]);
                    mma_f16(acc[1][2 * np + 1], ah[1], bh[2], bh[3]);
                }
            }
        }
    }

    // ---- epilogue: demodulate + store ----
    const int h = h0 + wm;
    float scl[8][2];
    #pragma unroll
    for (int nt = 0; nt < 8; nt++) {
        int oc = oc0 + wn * 64 + nt * 8 + tig * 2;
        scl[nt][0] = g_scale[b * OC + oc];
        scl[nt][1] = g_scale[b * OC + oc + 1];
    }
    #pragma unroll
    for (int mt = 0; mt < 2; mt++) {
        int w0 = mt * 16 + gr;
        #pragma unroll
        for (int nt = 0; nt < 8; nt++) {
            int oc = oc0 + wn * 64 + nt * 8 + tig * 2;
            size_t base0 = (((size_t)b * OC + oc) * HH + h) * WW;
            size_t base1 = base0 + (size_t)HH * WW;
            y[base0 + w0]     = acc[mt][nt][0] * scl[nt][0];
            y[base1 + w0]     = acc[mt][nt][1] * scl[nt][1];
            y[base0 + w0 + 8] = acc[mt][nt][2] * scl[nt][0];
            y[base1 + w0 + 8] = acc[mt][nt][3] * scl[nt][1];
        }
    }
}

// ---------------------------------------------------------------------------
extern "C" void kernel_launch(void* const* d_in, const int* in_sizes, int n_in,
                              void* d_out, int out_size) {
    const float* x       = (const float*)d_in[0];
    const float* w       = (const float*)d_in[1];
    const float* conv_w  = (const float*)d_in[2];
    const float* dense_w = (const float*)d_in[3];
    const float* dense_b = (const float*)d_in[4];
    float* y = (float*)d_out;

    style_kernel<<<BN, 256>>>(w, dense_w, dense_b);
    ss_kernel<<<(IC * OC) / 256, 256>>>(conv_w);
    demod_kernel<<<OC / 32, 256>>>();
    wtrans_kernel<<<dim3(IC / 32, OC / 32, 9), 256>>>(conv_w);
    xtrans_kernel<<<dim3(IC / 32, HH, BN), 256>>>(x);

    static bool attr_set = false;
    if (!attr_set) {
        cudaFuncSetAttribute(conv_mma_kernel,
                             cudaFuncAttributeMaxDynamicSharedMemorySize, SM_HALVES * 2);
        attr_set = true;
    }
    conv_mma_kernel<<<dim3(8, 4, BN), 256, SM_HALVES * 2>>>(y);
}